// round 8
// baseline (speedup 1.0000x reference)
#include <cuda_runtime.h>
#include <cuda_fp16.h>
#include <math_constants.h>
#include <cstdint>

#define N_NODES 8192
#define DEG     16
#define NBR     (DEG + 1)
#define F_IN    1024
#define F_OUT   128
#define H_HEADS 8
#define J_DIM   (H_HEADS * F_OUT)   // 1024
#define BK      32
#define NCHUNK  (F_IN / BK)         // 32

#define ROW_HF   40                  // fp16 per smem row (80 B, 16B-aligned, conflict-free)
#define ARR_HF   (128 * ROW_HF)      // fp16 per tile array (5120)
#define HS_STRIDE 132                // epilogue staging row stride (floats)

// Scratch (allocation-free rule: __device__ globals)
__device__ float g_h[N_NODES * J_DIM];                 // 32 MB projected features
__device__ __half g_Ahi[N_NODES * F_IN];               // 16 MB
__device__ __half g_Alo[N_NODES * F_IN];               // 16 MB
__device__ __half g_Whi[H_HEADS * F_OUT * F_IN];       // 2 MB  [h][o][k]
__device__ float g_sdst[H_HEADS * N_NODES];
__device__ float g_ssrc[H_HEADS * N_NODES];

// ---------------------------------------------------------------------------
static __device__ __forceinline__ uint32_t smem_u32(const void* p) {
    uint32_t a;
    asm("{ .reg .u64 t; cvta.to.shared.u64 t, %1; cvt.u32.u64 %0, t; }" : "=r"(a) : "l"(p));
    return a;
}
#define CP_ASYNC16(dst_u32, src_ptr) \
    asm volatile("cp.async.cg.shared.global [%0], [%1], 16;" :: "r"(dst_u32), "l"(src_ptr))
#define CP_COMMIT() asm volatile("cp.async.commit_group;" ::: "memory")
#define CP_WAIT(n)  asm volatile("cp.async.wait_group %0;" :: "n"(n) : "memory")

static __device__ __forceinline__ void mma_fp16(float* c, const uint32_t* a, const uint32_t* b) {
    asm volatile(
        "mma.sync.aligned.m16n8k16.row.col.f32.f16.f16.f32 "
        "{%0,%1,%2,%3}, {%4,%5,%6,%7}, {%8,%9}, {%0,%1,%2,%3};"
        : "+f"(c[0]), "+f"(c[1]), "+f"(c[2]), "+f"(c[3])
        : "r"(a[0]), "r"(a[1]), "r"(a[2]), "r"(a[3]), "r"(b[0]), "r"(b[1]));
}
static __device__ __forceinline__ void split_fp16(float v, __half& hi, __half& lo) {
    hi = __float2half_rn(v);
    lo = __float2half_rn(v - __half2float(hi));
}

// ---------------------------------------------------------------------------
// Kernel 0a: split features into fp16 hi/lo (same [n][k] layout)
// ---------------------------------------------------------------------------
__global__ void splitA(const float* __restrict__ A) {
    int idx = (blockIdx.x * blockDim.x + threadIdx.x) * 4;   // 4 floats per thread
    float4 v = *(const float4*)(A + idx);
    __half h0, h1, h2, h3, l0, l1, l2, l3;
    split_fp16(v.x, h0, l0); split_fp16(v.y, h1, l1);
    split_fp16(v.z, h2, l2); split_fp16(v.w, h3, l3);
    __half2* ph = (__half2*)(g_Ahi + idx);
    __half2* pl = (__half2*)(g_Alo + idx);
    ph[0] = __half2(h0, h1); ph[1] = __half2(h2, h3);
    pl[0] = __half2(l0, l1); pl[1] = __half2(l2, l3);
}

// ---------------------------------------------------------------------------
// Kernel 0b: W[h][k][o] -> Whi[h][o][k]  (transpose + fp16 round)
// ---------------------------------------------------------------------------
__global__ void splitW(const float* __restrict__ W) {
    __shared__ float t[32][33];
    int h = blockIdx.z, o0 = blockIdx.x * 32, k0 = blockIdx.y * 32;
    const float* Wp = W + (size_t)h * F_IN * F_OUT;
    size_t tbase = (size_t)h * F_OUT * F_IN;
    int tx = threadIdx.x, ty = threadIdx.y;
    #pragma unroll
    for (int r = 0; r < 32; r += 8)
        t[ty + r][tx] = Wp[(size_t)(k0 + ty + r) * F_OUT + o0 + tx];
    __syncthreads();
    #pragma unroll
    for (int r = 0; r < 32; r += 8) {
        float v = t[tx][ty + r];
        g_Whi[tbase + (size_t)(o0 + ty + r) * F_IN + k0 + tx] = __float2half_rn(v);
    }
}

// ---------------------------------------------------------------------------
// Kernel 1: fp16 2-pass mma.sync GEMM, tile 128x128(one head) x K=1024,
// cp.async double-buffered. C = A_hi*B_hi + A_lo*B_hi  (~= A*B_hi).
// Epilogue: bias, fused score dots, coalesced g_h store.
// ---------------------------------------------------------------------------
__global__ __launch_bounds__(256)
void gemm_tc(const float* __restrict__ bW,     // [H, F_OUT]
             const float* __restrict__ a_att)  // [H, 2*F_OUT]
{
    extern __shared__ float4 dsm4[];
    __half* sb = (__half*)dsm4;
    // layout: [buf][3 arrays: Ahi, Alo, Bhi] each ARR_HF fp16
    __half* Sa_hi[2] = { sb,              sb + 3 * ARR_HF };
    __half* Sa_lo[2] = { sb + 1 * ARR_HF, sb + 4 * ARR_HF };
    __half* Sb_hi[2] = { sb + 2 * ARR_HF, sb + 5 * ARR_HF };

    const int head = blockIdx.x;
    const int m0   = blockIdx.y * 128;
    const int tid  = threadIdx.x;
    const int wid  = tid >> 5;
    const int lane = tid & 31;
    const int warp_m = wid >> 2;          // 0..1
    const int warp_n = wid & 3;           // 0..3
    const int gid = lane >> 2;            // 0..7
    const int tig = lane & 3;             // 0..3

    const __half* Ah = g_Ahi + (size_t)m0 * F_IN;
    const __half* Al = g_Alo + (size_t)m0 * F_IN;
    const __half* Bh = g_Whi + (size_t)head * F_OUT * F_IN;

    // loader: each tile array = 128 rows x 32 fp16 = 512 x 16B; 2 slots/thread
    int ldr[2], lds_[2];
    #pragma unroll
    for (int j = 0; j < 2; j++) {
        int idx = tid + j * 256;
        ldr[j]  = idx >> 2;        // row 0..127
        lds_[j] = (idx & 3) * 8;   // fp16 col offset 0,8,16,24
    }

    auto issue_chunk = [&](int chunk) {
        int k0 = chunk * BK;
        int buf = chunk & 1;
        uint32_t ah_u = smem_u32(Sa_hi[buf]);
        uint32_t al_u = smem_u32(Sa_lo[buf]);
        uint32_t bh_u = smem_u32(Sb_hi[buf]);
        #pragma unroll
        for (int j = 0; j < 2; j++) {
            uint32_t doff = (uint32_t)(ldr[j] * ROW_HF + lds_[j]) * 2;
            size_t   soff = (size_t)ldr[j] * F_IN + k0 + lds_[j];
            CP_ASYNC16(ah_u + doff, Ah + soff);
            CP_ASYNC16(al_u + doff, Al + soff);
            CP_ASYNC16(bh_u + doff, Bh + soff);
        }
        CP_COMMIT();
    };

    float acc[4][4][4];
    #pragma unroll
    for (int i = 0; i < 4; i++)
        #pragma unroll
        for (int j = 0; j < 4; j++)
            #pragma unroll
            for (int r = 0; r < 4; r++) acc[i][j][r] = 0.f;

    issue_chunk(0);
    issue_chunk(1);

    for (int i = 0; i < NCHUNK; i++) {
        if (i < NCHUNK - 1) { CP_WAIT(1); } else { CP_WAIT(0); }
        __syncthreads();
        const int buf = i & 1;
        const uint32_t* ah = (const uint32_t*)Sa_hi[buf];
        const uint32_t* al = (const uint32_t*)Sa_lo[buf];
        const uint32_t* bh = (const uint32_t*)Sb_hi[buf];

        #pragma unroll
        for (int ks = 0; ks < 2; ks++) {          // K=16 per mma
            const int kw = ks * 8;                // word offset (fp16 pairs)

            uint32_t bfh[4][2];
            #pragma unroll
            for (int nt = 0; nt < 4; nt++) {
                int n = warp_n * 32 + nt * 8 + gid;
                int w0 = n * (ROW_HF / 2) + kw + tig;
                bfh[nt][0] = bh[w0];     bfh[nt][1] = bh[w0 + 4];
            }
            uint32_t afh[4][4], afl[4][4];
            #pragma unroll
            for (int mt = 0; mt < 4; mt++) {
                int row = warp_m * 64 + mt * 16 + gid;
                int w0 = row * (ROW_HF / 2) + kw + tig;
                int w1 = (row + 8) * (ROW_HF / 2) + kw + tig;
                afh[mt][0] = ah[w0]; afh[mt][1] = ah[w1];
                afh[mt][2] = ah[w0 + 4]; afh[mt][3] = ah[w1 + 4];
                afl[mt][0] = al[w0]; afl[mt][1] = al[w1];
                afl[mt][2] = al[w0 + 4]; afl[mt][3] = al[w1 + 4];
            }

            #pragma unroll
            for (int mt = 0; mt < 4; mt++)
                #pragma unroll
                for (int nt = 0; nt < 4; nt++)
                    mma_fp16(acc[mt][nt], afh[mt], bfh[nt]);   // hi*Bhi
            #pragma unroll
            for (int mt = 0; mt < 4; mt++)
                #pragma unroll
                for (int nt = 0; nt < 4; nt++)
                    mma_fp16(acc[mt][nt], afl[mt], bfh[nt]);   // lo*Bhi
        }
        __syncthreads();
        if (i + 2 < NCHUNK) issue_chunk(i + 2);
    }

    // ---- epilogue: stage (acc+bias) into smem, then dots + coalesced stores ----
    float* hs = (float*)dsm4;   // 128 x HS_STRIDE floats = 67584 B <= dsmem
    const float* bias = bW + head * F_OUT;
    #pragma unroll
    for (int mt = 0; mt < 4; mt++) {
        #pragma unroll
        for (int nt = 0; nt < 4; nt++) {
            int row = warp_m * 64 + mt * 16 + gid;
            int col = warp_n * 32 + nt * 8 + 2 * tig;
            float b0 = bias[col], b1 = bias[col + 1];
            float2 v0 = make_float2(acc[mt][nt][0] + b0, acc[mt][nt][1] + b1);
            float2 v1 = make_float2(acc[mt][nt][2] + b0, acc[mt][nt][3] + b1);
            *(float2*)&hs[(size_t)row * HS_STRIDE + col]       = v0;
            *(float2*)&hs[(size_t)(row + 8) * HS_STRIDE + col] = v1;
        }
    }
    __syncthreads();

    // score dots: warp w owns rows w*16 .. w*16+15
    const float* ad = a_att + head * 2 * F_OUT;
    const float* as = ad + F_OUT;
    #pragma unroll
    for (int it = 0; it < 16; it++) {
        int row = wid * 16 + it;
        float pd = 0.f, ps = 0.f;
        #pragma unroll
        for (int j = 0; j < 4; j++) {
            int c = lane + 32 * j;
            float v = hs[(size_t)row * HS_STRIDE + c];
            pd = fmaf(v, ad[c], pd);
            ps = fmaf(v, as[c], ps);
        }
        #pragma unroll
        for (int off = 16; off > 0; off >>= 1) {
            pd += __shfl_xor_sync(0xFFFFFFFFu, pd, off);
            ps += __shfl_xor_sync(0xFFFFFFFFu, ps, off);
        }
        if (lane == 0) {
            g_sdst[head * N_NODES + m0 + row] = pd;
            g_ssrc[head * N_NODES + m0 + row] = ps;
        }
    }

    // coalesced g_h stores: 4096 float4
    #pragma unroll
    for (int it = 0; it < 16; it++) {
        int idx = tid + it * 256;
        int row = idx >> 5;
        int c4  = (idx & 31) * 4;
        float4 v = *(const float4*)&hs[(size_t)row * HS_STRIDE + c4];
        *(float4*)(g_h + (size_t)(m0 + row) * J_DIM + head * F_OUT + c4) = v;
    }
}

// ---------------------------------------------------------------------------
// Kernel 2: softmax over 17 neighbors + weighted gather-aggregate.
// One warp per (h,n).
// ---------------------------------------------------------------------------
__global__ void attn_kernel(const int* __restrict__ adj,
                            const float* __restrict__ ba,
                            float* __restrict__ out)
{
    int w = (blockIdx.x * blockDim.x + threadIdx.x) >> 5;
    int lane = threadIdx.x & 31;
    if (w >= H_HEADS * N_NODES) return;
    int h = w & (H_HEADS - 1);
    int n = w >> 3;

    int nbr = 0;
    float sc = -CUDART_INF_F;
    if (lane < NBR) {
        nbr = (lane < DEG) ? adj[n * DEG + lane] : n;
        float x = g_sdst[h * N_NODES + n] + g_ssrc[h * N_NODES + nbr] + ba[h];
        sc = (x > 0.f) ? x : 0.2f * x;
    }

    float m = sc;
    #pragma unroll
    for (int off = 16; off > 0; off >>= 1)
        m = fmaxf(m, __shfl_xor_sync(0xFFFFFFFFu, m, off));

    float e = (lane < NBR) ? __expf(sc - m) : 0.f;
    float s = e;
    #pragma unroll
    for (int off = 16; off > 0; off >>= 1)
        s += __shfl_xor_sync(0xFFFFFFFFu, s, off);

    float alpha = e / s;

    float4 acc = make_float4(0.f, 0.f, 0.f, 0.f);
    #pragma unroll
    for (int d = 0; d < NBR; d++) {
        int nb = __shfl_sync(0xFFFFFFFFu, nbr, d);
        float al = __shfl_sync(0xFFFFFFFFu, alpha, d);
        float4 v = *(const float4*)(g_h + (size_t)nb * J_DIM + h * F_OUT + lane * 4);
        acc.x = fmaf(al, v.x, acc.x);
        acc.y = fmaf(al, v.y, acc.y);
        acc.z = fmaf(al, v.z, acc.z);
        acc.w = fmaf(al, v.w, acc.w);
    }
    *(float4*)(out + (size_t)n * J_DIM + h * F_OUT + lane * 4) = acc;
}

// ---------------------------------------------------------------------------
extern "C" void kernel_launch(void* const* d_in, const int* in_sizes, int n_in,
                              void* d_out, int out_size)
{
    const float* features = (const float*)d_in[0];   // [8192, 1024]
    const int*   adj      = (const int*)  d_in[1];   // [8192, 16]
    const float* W        = (const float*)d_in[2];   // [8, 1024, 128]
    const float* bW       = (const float*)d_in[3];   // [8, 128]
    const float* a        = (const float*)d_in[4];   // [8, 256]
    const float* ba       = (const float*)d_in[5];   // [8]
    float* out = (float*)d_out;                      // [8192, 1024]

    // 0) split features into fp16 hi/lo; W -> fp16 K-major
    splitA<<<(N_NODES * F_IN) / (256 * 4), 256>>>(features);
    splitW<<<dim3(F_OUT / 32, F_IN / 32, H_HEADS), dim3(32, 8)>>>(W);

    // 1) fp16 2-pass mma.sync projection GEMM (+ fused bias & score dots)
    const int dsmem = 68608;   // >= max(6*ARR_HF*2 = 61440, epilogue 67584)
    cudaFuncSetAttribute(gemm_tc, cudaFuncAttributeMaxDynamicSharedMemorySize, dsmem);
    gemm_tc<<<dim3(H_HEADS, N_NODES / 128), 256, dsmem>>>(bW, a);

    // 2) softmax + aggregate
    int warps = H_HEADS * N_NODES;
    attn_kernel<<<(warps * 32) / 256, 256>>>(adj, ba, out);
}

// round 10
// speedup vs baseline: 1.8166x; 1.8166x over previous
#include <cuda_runtime.h>
#include <cuda_fp16.h>
#include <math_constants.h>
#include <cstdint>

#define N_NODES 8192
#define DEG     16
#define NBR     (DEG + 1)
#define F_IN    1024
#define F_OUT   128
#define H_HEADS 8
#define J_DIM   (H_HEADS * F_OUT)   // 1024
#define BK      32
#define NCHUNK  (F_IN / BK)         // 32

#define ROW_HF   40                  // fp16 per smem row (80 B, 16B-aligned, conflict-free)
#define ARR_HF   (128 * ROW_HF)      // fp16 per tile array (5120)
#define HS_STRIDE 132                // epilogue staging row stride (floats)

// Scratch (allocation-free rule: __device__ globals)
__device__ __half g_hh[N_NODES * J_DIM];               // 16 MB projected features (fp16)
__device__ __half g_Ahi[N_NODES * F_IN];               // 16 MB
__device__ __half g_Alo[N_NODES * F_IN];               // 16 MB
__device__ __half g_Whi[H_HEADS * F_OUT * F_IN];       // 2 MB  [h][o][k]
__device__ float g_sdst[H_HEADS * N_NODES];
__device__ float g_ssrc[H_HEADS * N_NODES];

// ---------------------------------------------------------------------------
static __device__ __forceinline__ uint32_t smem_u32(const void* p) {
    uint32_t a;
    asm("{ .reg .u64 t; cvta.to.shared.u64 t, %1; cvt.u32.u64 %0, t; }" : "=r"(a) : "l"(p));
    return a;
}
#define CP_ASYNC16(dst_u32, src_ptr) \
    asm volatile("cp.async.cg.shared.global [%0], [%1], 16;" :: "r"(dst_u32), "l"(src_ptr))
#define CP_COMMIT() asm volatile("cp.async.commit_group;" ::: "memory")
#define CP_WAIT(n)  asm volatile("cp.async.wait_group %0;" :: "n"(n) : "memory")

static __device__ __forceinline__ void mma_fp16(float* c, const uint32_t* a, const uint32_t* b) {
    asm volatile(
        "mma.sync.aligned.m16n8k16.row.col.f32.f16.f16.f32 "
        "{%0,%1,%2,%3}, {%4,%5,%6,%7}, {%8,%9}, {%0,%1,%2,%3};"
        : "+f"(c[0]), "+f"(c[1]), "+f"(c[2]), "+f"(c[3])
        : "r"(a[0]), "r"(a[1]), "r"(a[2]), "r"(a[3]), "r"(b[0]), "r"(b[1]));
}
static __device__ __forceinline__ void split_fp16(float v, __half& hi, __half& lo) {
    hi = __float2half_rn(v);
    lo = __float2half_rn(v - __half2float(hi));
}

// ---------------------------------------------------------------------------
// Kernel 0a: split features into fp16 hi/lo (same [n][k] layout)
// ---------------------------------------------------------------------------
__global__ void splitA(const float* __restrict__ A) {
    int idx = (blockIdx.x * blockDim.x + threadIdx.x) * 4;   // 4 floats per thread
    float4 v = *(const float4*)(A + idx);
    __half h0, h1, h2, h3, l0, l1, l2, l3;
    split_fp16(v.x, h0, l0); split_fp16(v.y, h1, l1);
    split_fp16(v.z, h2, l2); split_fp16(v.w, h3, l3);
    __half2* ph = (__half2*)(g_Ahi + idx);
    __half2* pl = (__half2*)(g_Alo + idx);
    ph[0] = __half2(h0, h1); ph[1] = __half2(h2, h3);
    pl[0] = __half2(l0, l1); pl[1] = __half2(l2, l3);
}

// ---------------------------------------------------------------------------
// Kernel 0b: W[h][k][o] -> Whi[h][o][k]  (transpose + fp16 round)
// ---------------------------------------------------------------------------
__global__ void splitW(const float* __restrict__ W) {
    __shared__ float t[32][33];
    int h = blockIdx.z, o0 = blockIdx.x * 32, k0 = blockIdx.y * 32;
    const float* Wp = W + (size_t)h * F_IN * F_OUT;
    size_t tbase = (size_t)h * F_OUT * F_IN;
    int tx = threadIdx.x, ty = threadIdx.y;
    #pragma unroll
    for (int r = 0; r < 32; r += 8)
        t[ty + r][tx] = Wp[(size_t)(k0 + ty + r) * F_OUT + o0 + tx];
    __syncthreads();
    #pragma unroll
    for (int r = 0; r < 32; r += 8) {
        float v = t[tx][ty + r];
        g_Whi[tbase + (size_t)(o0 + ty + r) * F_IN + k0 + tx] = __float2half_rn(v);
    }
}

// ---------------------------------------------------------------------------
// Kernel 1: fp16 2-pass mma.sync GEMM, tile 128x128(one head) x K=1024,
// cp.async double-buffered. C = A_hi*B_hi + A_lo*B_hi  (~= A*B_hi).
// Epilogue: bias, fused score dots (fp32), fp16 coalesced g_hh store.
// ---------------------------------------------------------------------------
__global__ __launch_bounds__(256)
void gemm_tc(const float* __restrict__ bW,     // [H, F_OUT]
             const float* __restrict__ a_att)  // [H, 2*F_OUT]
{
    extern __shared__ float4 dsm4[];
    __half* sb = (__half*)dsm4;
    // layout: [buf][3 arrays: Ahi, Alo, Bhi] each ARR_HF fp16
    __half* Sa_hi[2] = { sb,              sb + 3 * ARR_HF };
    __half* Sa_lo[2] = { sb + 1 * ARR_HF, sb + 4 * ARR_HF };
    __half* Sb_hi[2] = { sb + 2 * ARR_HF, sb + 5 * ARR_HF };

    const int head = blockIdx.x;
    const int m0   = blockIdx.y * 128;
    const int tid  = threadIdx.x;
    const int wid  = tid >> 5;
    const int lane = tid & 31;
    const int warp_m = wid >> 2;          // 0..1
    const int warp_n = wid & 3;           // 0..3
    const int gid = lane >> 2;            // 0..7
    const int tig = lane & 3;             // 0..3

    const __half* Ah = g_Ahi + (size_t)m0 * F_IN;
    const __half* Al = g_Alo + (size_t)m0 * F_IN;
    const __half* Bh = g_Whi + (size_t)head * F_OUT * F_IN;

    // loader: each tile array = 128 rows x 32 fp16 = 512 x 16B; 2 slots/thread
    int ldr[2], lds_[2];
    #pragma unroll
    for (int j = 0; j < 2; j++) {
        int idx = tid + j * 256;
        ldr[j]  = idx >> 2;        // row 0..127
        lds_[j] = (idx & 3) * 8;   // fp16 col offset 0,8,16,24
    }

    auto issue_chunk = [&](int chunk) {
        int k0 = chunk * BK;
        int buf = chunk & 1;
        uint32_t ah_u = smem_u32(Sa_hi[buf]);
        uint32_t al_u = smem_u32(Sa_lo[buf]);
        uint32_t bh_u = smem_u32(Sb_hi[buf]);
        #pragma unroll
        for (int j = 0; j < 2; j++) {
            uint32_t doff = (uint32_t)(ldr[j] * ROW_HF + lds_[j]) * 2;
            size_t   soff = (size_t)ldr[j] * F_IN + k0 + lds_[j];
            CP_ASYNC16(ah_u + doff, Ah + soff);
            CP_ASYNC16(al_u + doff, Al + soff);
            CP_ASYNC16(bh_u + doff, Bh + soff);
        }
        CP_COMMIT();
    };

    float acc[4][4][4];
    #pragma unroll
    for (int i = 0; i < 4; i++)
        #pragma unroll
        for (int j = 0; j < 4; j++)
            #pragma unroll
            for (int r = 0; r < 4; r++) acc[i][j][r] = 0.f;

    issue_chunk(0);
    issue_chunk(1);

    for (int i = 0; i < NCHUNK; i++) {
        if (i < NCHUNK - 1) { CP_WAIT(1); } else { CP_WAIT(0); }
        __syncthreads();
        const int buf = i & 1;
        const uint32_t* ah = (const uint32_t*)Sa_hi[buf];
        const uint32_t* al = (const uint32_t*)Sa_lo[buf];
        const uint32_t* bh = (const uint32_t*)Sb_hi[buf];

        #pragma unroll
        for (int ks = 0; ks < 2; ks++) {          // K=16 per mma
            const int kw = ks * 8;                // word offset (fp16 pairs)

            uint32_t bfh[4][2];
            #pragma unroll
            for (int nt = 0; nt < 4; nt++) {
                int n = warp_n * 32 + nt * 8 + gid;
                int w0 = n * (ROW_HF / 2) + kw + tig;
                bfh[nt][0] = bh[w0];     bfh[nt][1] = bh[w0 + 4];
            }
            uint32_t afh[4][4], afl[4][4];
            #pragma unroll
            for (int mt = 0; mt < 4; mt++) {
                int row = warp_m * 64 + mt * 16 + gid;
                int w0 = row * (ROW_HF / 2) + kw + tig;
                int w1 = (row + 8) * (ROW_HF / 2) + kw + tig;
                afh[mt][0] = ah[w0]; afh[mt][1] = ah[w1];
                afh[mt][2] = ah[w0 + 4]; afh[mt][3] = ah[w1 + 4];
                afl[mt][0] = al[w0]; afl[mt][1] = al[w1];
                afl[mt][2] = al[w0 + 4]; afl[mt][3] = al[w1 + 4];
            }

            #pragma unroll
            for (int mt = 0; mt < 4; mt++)
                #pragma unroll
                for (int nt = 0; nt < 4; nt++)
                    mma_fp16(acc[mt][nt], afh[mt], bfh[nt]);   // hi*Bhi
            #pragma unroll
            for (int mt = 0; mt < 4; mt++)
                #pragma unroll
                for (int nt = 0; nt < 4; nt++)
                    mma_fp16(acc[mt][nt], afl[mt], bfh[nt]);   // lo*Bhi
        }
        __syncthreads();
        if (i + 2 < NCHUNK) issue_chunk(i + 2);
    }

    // ---- epilogue: stage (acc+bias) into smem, then dots + fp16 stores ----
    float* hs = (float*)dsm4;   // 128 x HS_STRIDE floats = 67584 B <= dsmem
    const float* bias = bW + head * F_OUT;
    #pragma unroll
    for (int mt = 0; mt < 4; mt++) {
        #pragma unroll
        for (int nt = 0; nt < 4; nt++) {
            int row = warp_m * 64 + mt * 16 + gid;
            int col = warp_n * 32 + nt * 8 + 2 * tig;
            float b0 = bias[col], b1 = bias[col + 1];
            float2 v0 = make_float2(acc[mt][nt][0] + b0, acc[mt][nt][1] + b1);
            float2 v1 = make_float2(acc[mt][nt][2] + b0, acc[mt][nt][3] + b1);
            *(float2*)&hs[(size_t)row * HS_STRIDE + col]       = v0;
            *(float2*)&hs[(size_t)(row + 8) * HS_STRIDE + col] = v1;
        }
    }
    __syncthreads();

    // score dots (fp32 smem values): warp w owns rows w*16 .. w*16+15
    const float* ad = a_att + head * 2 * F_OUT;
    const float* as = ad + F_OUT;
    #pragma unroll
    for (int it = 0; it < 16; it++) {
        int row = wid * 16 + it;
        float pd = 0.f, ps = 0.f;
        #pragma unroll
        for (int j = 0; j < 4; j++) {
            int c = lane + 32 * j;
            float v = hs[(size_t)row * HS_STRIDE + c];
            pd = fmaf(v, ad[c], pd);
            ps = fmaf(v, as[c], ps);
        }
        #pragma unroll
        for (int off = 16; off > 0; off >>= 1) {
            pd += __shfl_xor_sync(0xFFFFFFFFu, pd, off);
            ps += __shfl_xor_sync(0xFFFFFFFFu, ps, off);
        }
        if (lane == 0) {
            g_sdst[head * N_NODES + m0 + row] = pd;
            g_ssrc[head * N_NODES + m0 + row] = ps;
        }
    }

    // coalesced fp16 g_hh stores: 4096 x 4 halves (8 B each)
    #pragma unroll
    for (int it = 0; it < 16; it++) {
        int idx = tid + it * 256;
        int row = idx >> 5;
        int c4  = (idx & 31) * 4;
        float4 v = *(const float4*)&hs[(size_t)row * HS_STRIDE + c4];
        __half2 p0 = __floats2half2_rn(v.x, v.y);
        __half2 p1 = __floats2half2_rn(v.z, v.w);
        uint2 pk;
        pk.x = *(uint32_t*)&p0;
        pk.y = *(uint32_t*)&p1;
        *(uint2*)(g_hh + (size_t)(m0 + row) * J_DIM + head * F_OUT + c4) = pk;
    }
}

// ---------------------------------------------------------------------------
// Kernel 2: softmax over 17 neighbors + weighted gather-aggregate (fp16 gather).
// One warp per (h,n).
// ---------------------------------------------------------------------------
__global__ void attn_kernel(const int* __restrict__ adj,
                            const float* __restrict__ ba,
                            float* __restrict__ out)
{
    int w = (blockIdx.x * blockDim.x + threadIdx.x) >> 5;
    int lane = threadIdx.x & 31;
    if (w >= H_HEADS * N_NODES) return;
    int h = w & (H_HEADS - 1);
    int n = w >> 3;

    int nbr = 0;
    float sc = -CUDART_INF_F;
    if (lane < NBR) {
        nbr = (lane < DEG) ? adj[n * DEG + lane] : n;
        float x = g_sdst[h * N_NODES + n] + g_ssrc[h * N_NODES + nbr] + ba[h];
        sc = (x > 0.f) ? x : 0.2f * x;
    }

    float m = sc;
    #pragma unroll
    for (int off = 16; off > 0; off >>= 1)
        m = fmaxf(m, __shfl_xor_sync(0xFFFFFFFFu, m, off));

    float e = (lane < NBR) ? __expf(sc - m) : 0.f;
    float s = e;
    #pragma unroll
    for (int off = 16; off > 0; off >>= 1)
        s += __shfl_xor_sync(0xFFFFFFFFu, s, off);

    float alpha = e / s;

    float4 acc = make_float4(0.f, 0.f, 0.f, 0.f);
    #pragma unroll
    for (int d = 0; d < NBR; d++) {
        int nb = __shfl_sync(0xFFFFFFFFu, nbr, d);
        float al = __shfl_sync(0xFFFFFFFFu, alpha, d);
        uint2 pk = *(const uint2*)(g_hh + (size_t)nb * J_DIM + h * F_OUT + lane * 4);
        __half2 p0 = *(__half2*)&pk.x;
        __half2 p1 = *(__half2*)&pk.y;
        float2 f0 = __half22float2(p0);
        float2 f1 = __half22float2(p1);
        acc.x = fmaf(al, f0.x, acc.x);
        acc.y = fmaf(al, f0.y, acc.y);
        acc.z = fmaf(al, f1.x, acc.z);
        acc.w = fmaf(al, f1.y, acc.w);
    }
    *(float4*)(out + (size_t)n * J_DIM + h * F_OUT + lane * 4) = acc;
}

// ---------------------------------------------------------------------------
extern "C" void kernel_launch(void* const* d_in, const int* in_sizes, int n_in,
                              void* d_out, int out_size)
{
    const float* features = (const float*)d_in[0];   // [8192, 1024]
    const int*   adj      = (const int*)  d_in[1];   // [8192, 16]
    const float* W        = (const float*)d_in[2];   // [8, 1024, 128]
    const float* bW       = (const float*)d_in[3];   // [8, 128]
    const float* a        = (const float*)d_in[4];   // [8, 256]
    const float* ba       = (const float*)d_in[5];   // [8]
    float* out = (float*)d_out;                      // [8192, 1024]

    // 0) split features into fp16 hi/lo; W -> fp16 K-major
    splitA<<<(N_NODES * F_IN) / (256 * 4), 256>>>(features);
    splitW<<<dim3(F_OUT / 32, F_IN / 32, H_HEADS), dim3(32, 8)>>>(W);

    // 1) fp16 2-pass mma.sync projection GEMM (+ fused bias & score dots)
    const int dsmem = 68608;   // >= max(6*ARR_HF*2 = 61440, epilogue 67584)
    cudaFuncSetAttribute(gemm_tc, cudaFuncAttributeMaxDynamicSharedMemorySize, dsmem);
    gemm_tc<<<dim3(H_HEADS, N_NODES / 128), 256, dsmem>>>(bW, a);

    // 2) softmax + aggregate (fp16 gather)
    int warps = H_HEADS * N_NODES;
    attn_kernel<<<(warps * 32) / 256, 256>>>(adj, ba, out);
}

// round 11
// speedup vs baseline: 2.9796x; 1.6402x over previous
#include <cuda_runtime.h>
#include <cuda_fp16.h>
#include <math_constants.h>
#include <cstdint>

#define N_NODES 8192
#define DEG     16
#define NBR     (DEG + 1)
#define F_IN    1024
#define F_OUT   128
#define H_HEADS 8
#define J_DIM   (H_HEADS * F_OUT)   // 1024
#define BK      32
#define NCHUNK  (F_IN / BK)         // 32

#define ROW_HF   40                  // fp16 per smem row (80 B, 16B-aligned, conflict-free)
#define ARR_HF   (128 * ROW_HF)      // fp16 per tile array (5120)
#define HS_STRIDE 132                // epilogue staging row stride (floats)

// Scratch (allocation-free rule: __device__ globals)
__device__ __half g_hh[N_NODES * J_DIM];               // 16 MB projected features (fp16)
__device__ __half g_Ahi[N_NODES * F_IN];               // 16 MB
__device__ __half g_Whi[H_HEADS * F_OUT * F_IN];       // 2 MB  [h][o][k]
__device__ float g_sdst[H_HEADS * N_NODES];
__device__ float g_ssrc[H_HEADS * N_NODES];

// ---------------------------------------------------------------------------
static __device__ __forceinline__ uint32_t smem_u32(const void* p) {
    uint32_t a;
    asm("{ .reg .u64 t; cvta.to.shared.u64 t, %1; cvt.u32.u64 %0, t; }" : "=r"(a) : "l"(p));
    return a;
}
#define CP_ASYNC16(dst_u32, src_ptr) \
    asm volatile("cp.async.cg.shared.global [%0], [%1], 16;" :: "r"(dst_u32), "l"(src_ptr))
#define CP_COMMIT() asm volatile("cp.async.commit_group;" ::: "memory")
#define CP_WAIT(n)  asm volatile("cp.async.wait_group %0;" :: "n"(n) : "memory")

static __device__ __forceinline__ void mma_fp16(float* c, const uint32_t* a, const uint32_t* b) {
    asm volatile(
        "mma.sync.aligned.m16n8k16.row.col.f32.f16.f16.f32 "
        "{%0,%1,%2,%3}, {%4,%5,%6,%7}, {%8,%9}, {%0,%1,%2,%3};"
        : "+f"(c[0]), "+f"(c[1]), "+f"(c[2]), "+f"(c[3])
        : "r"(a[0]), "r"(a[1]), "r"(a[2]), "r"(a[3]), "r"(b[0]), "r"(b[1]));
}

// ---------------------------------------------------------------------------
// Kernel 0a: cast features to fp16 (same [n][k] layout)
// ---------------------------------------------------------------------------
__global__ void castA(const float* __restrict__ A) {
    int idx = (blockIdx.x * blockDim.x + threadIdx.x) * 4;   // 4 floats per thread
    float4 v = *(const float4*)(A + idx);
    __half2* ph = (__half2*)(g_Ahi + idx);
    ph[0] = __floats2half2_rn(v.x, v.y);
    ph[1] = __floats2half2_rn(v.z, v.w);
}

// ---------------------------------------------------------------------------
// Kernel 0b: W[h][k][o] -> Whi[h][o][k]  (transpose + fp16 round)
// ---------------------------------------------------------------------------
__global__ void castW(const float* __restrict__ W) {
    __shared__ float t[32][33];
    int h = blockIdx.z, o0 = blockIdx.x * 32, k0 = blockIdx.y * 32;
    const float* Wp = W + (size_t)h * F_IN * F_OUT;
    size_t tbase = (size_t)h * F_OUT * F_IN;
    int tx = threadIdx.x, ty = threadIdx.y;
    #pragma unroll
    for (int r = 0; r < 32; r += 8)
        t[ty + r][tx] = Wp[(size_t)(k0 + ty + r) * F_OUT + o0 + tx];
    __syncthreads();
    #pragma unroll
    for (int r = 0; r < 32; r += 8) {
        float v = t[tx][ty + r];
        g_Whi[tbase + (size_t)(o0 + ty + r) * F_IN + k0 + tx] = __float2half_rn(v);
    }
}

// ---------------------------------------------------------------------------
// Kernel 1: single-pass fp16 mma.sync GEMM, tile 128x128(one head) x K=1024,
// cp.async double-buffered. C = A_hi * B_hi.
// Epilogue: bias, fused score dots (fp32), fp16 coalesced g_hh store.
// ---------------------------------------------------------------------------
__global__ __launch_bounds__(256)
void gemm_tc(const float* __restrict__ bW,     // [H, F_OUT]
             const float* __restrict__ a_att)  // [H, 2*F_OUT]
{
    extern __shared__ float4 dsm4[];
    __half* sb = (__half*)dsm4;
    // layout: [buf][2 arrays: Ahi, Bhi] each ARR_HF fp16
    __half* Sa_hi[2] = { sb,              sb + 2 * ARR_HF };
    __half* Sb_hi[2] = { sb + 1 * ARR_HF, sb + 3 * ARR_HF };

    const int head = blockIdx.x;
    const int m0   = blockIdx.y * 128;
    const int tid  = threadIdx.x;
    const int wid  = tid >> 5;
    const int lane = tid & 31;
    const int warp_m = wid >> 2;          // 0..1
    const int warp_n = wid & 3;           // 0..3
    const int gid = lane >> 2;            // 0..7
    const int tig = lane & 3;             // 0..3

    const __half* Ah = g_Ahi + (size_t)m0 * F_IN;
    const __half* Bh = g_Whi + (size_t)head * F_OUT * F_IN;

    // loader: each tile array = 128 rows x 32 fp16 = 512 x 16B; 2 slots/thread
    int ldr[2], lds_[2];
    #pragma unroll
    for (int j = 0; j < 2; j++) {
        int idx = tid + j * 256;
        ldr[j]  = idx >> 2;        // row 0..127
        lds_[j] = (idx & 3) * 8;   // fp16 col offset 0,8,16,24
    }

    auto issue_chunk = [&](int chunk) {
        int k0 = chunk * BK;
        int buf = chunk & 1;
        uint32_t ah_u = smem_u32(Sa_hi[buf]);
        uint32_t bh_u = smem_u32(Sb_hi[buf]);
        #pragma unroll
        for (int j = 0; j < 2; j++) {
            uint32_t doff = (uint32_t)(ldr[j] * ROW_HF + lds_[j]) * 2;
            size_t   soff = (size_t)ldr[j] * F_IN + k0 + lds_[j];
            CP_ASYNC16(ah_u + doff, Ah + soff);
            CP_ASYNC16(bh_u + doff, Bh + soff);
        }
        CP_COMMIT();
    };

    float acc[4][4][4];
    #pragma unroll
    for (int i = 0; i < 4; i++)
        #pragma unroll
        for (int j = 0; j < 4; j++)
            #pragma unroll
            for (int r = 0; r < 4; r++) acc[i][j][r] = 0.f;

    issue_chunk(0);
    issue_chunk(1);

    for (int i = 0; i < NCHUNK; i++) {
        if (i < NCHUNK - 1) { CP_WAIT(1); } else { CP_WAIT(0); }
        __syncthreads();
        const int buf = i & 1;
        const uint32_t* ah = (const uint32_t*)Sa_hi[buf];
        const uint32_t* bh = (const uint32_t*)Sb_hi[buf];

        #pragma unroll
        for (int ks = 0; ks < 2; ks++) {          // K=16 per mma
            const int kw = ks * 8;                // word offset (fp16 pairs)

            uint32_t bfh[4][2];
            #pragma unroll
            for (int nt = 0; nt < 4; nt++) {
                int n = warp_n * 32 + nt * 8 + gid;
                int w0 = n * (ROW_HF / 2) + kw + tig;
                bfh[nt][0] = bh[w0];     bfh[nt][1] = bh[w0 + 4];
            }
            uint32_t afh[4][4];
            #pragma unroll
            for (int mt = 0; mt < 4; mt++) {
                int row = warp_m * 64 + mt * 16 + gid;
                int w0 = row * (ROW_HF / 2) + kw + tig;
                int w1 = (row + 8) * (ROW_HF / 2) + kw + tig;
                afh[mt][0] = ah[w0]; afh[mt][1] = ah[w1];
                afh[mt][2] = ah[w0 + 4]; afh[mt][3] = ah[w1 + 4];
            }

            #pragma unroll
            for (int mt = 0; mt < 4; mt++)
                #pragma unroll
                for (int nt = 0; nt < 4; nt++)
                    mma_fp16(acc[mt][nt], afh[mt], bfh[nt]);
        }
        __syncthreads();
        if (i + 2 < NCHUNK) issue_chunk(i + 2);
    }

    // ---- epilogue: stage (acc+bias) into smem, then dots + fp16 stores ----
    float* hs = (float*)dsm4;   // 128 x HS_STRIDE floats = 67584 B <= dsmem
    const float* bias = bW + head * F_OUT;
    #pragma unroll
    for (int mt = 0; mt < 4; mt++) {
        #pragma unroll
        for (int nt = 0; nt < 4; nt++) {
            int row = warp_m * 64 + mt * 16 + gid;
            int col = warp_n * 32 + nt * 8 + 2 * tig;
            float b0 = bias[col], b1 = bias[col + 1];
            float2 v0 = make_float2(acc[mt][nt][0] + b0, acc[mt][nt][1] + b1);
            float2 v1 = make_float2(acc[mt][nt][2] + b0, acc[mt][nt][3] + b1);
            *(float2*)&hs[(size_t)row * HS_STRIDE + col]       = v0;
            *(float2*)&hs[(size_t)(row + 8) * HS_STRIDE + col] = v1;
        }
    }
    __syncthreads();

    // score dots (fp32 smem values): warp w owns rows w*16 .. w*16+15
    const float* ad = a_att + head * 2 * F_OUT;
    const float* as = ad + F_OUT;
    #pragma unroll
    for (int it = 0; it < 16; it++) {
        int row = wid * 16 + it;
        float pd = 0.f, ps = 0.f;
        #pragma unroll
        for (int j = 0; j < 4; j++) {
            int c = lane + 32 * j;
            float v = hs[(size_t)row * HS_STRIDE + c];
            pd = fmaf(v, ad[c], pd);
            ps = fmaf(v, as[c], ps);
        }
        #pragma unroll
        for (int off = 16; off > 0; off >>= 1) {
            pd += __shfl_xor_sync(0xFFFFFFFFu, pd, off);
            ps += __shfl_xor_sync(0xFFFFFFFFu, ps, off);
        }
        if (lane == 0) {
            g_sdst[head * N_NODES + m0 + row] = pd;
            g_ssrc[head * N_NODES + m0 + row] = ps;
        }
    }

    // coalesced fp16 g_hh stores: 4096 x 4 halves (8 B each)
    #pragma unroll
    for (int it = 0; it < 16; it++) {
        int idx = tid + it * 256;
        int row = idx >> 5;
        int c4  = (idx & 31) * 4;
        float4 v = *(const float4*)&hs[(size_t)row * HS_STRIDE + c4];
        __half2 p0 = __floats2half2_rn(v.x, v.y);
        __half2 p1 = __floats2half2_rn(v.z, v.w);
        uint2 pk;
        pk.x = *(uint32_t*)&p0;
        pk.y = *(uint32_t*)&p1;
        *(uint2*)(g_hh + (size_t)(m0 + row) * J_DIM + head * F_OUT + c4) = pk;
    }
}

// ---------------------------------------------------------------------------
// Kernel 2: softmax over 17 neighbors + weighted gather-aggregate (fp16 gather).
// One warp per (h,n).
// ---------------------------------------------------------------------------
__global__ void attn_kernel(const int* __restrict__ adj,
                            const float* __restrict__ ba,
                            float* __restrict__ out)
{
    int w = (blockIdx.x * blockDim.x + threadIdx.x) >> 5;
    int lane = threadIdx.x & 31;
    if (w >= H_HEADS * N_NODES) return;
    int h = w & (H_HEADS - 1);
    int n = w >> 3;

    int nbr = 0;
    float sc = -CUDART_INF_F;
    if (lane < NBR) {
        nbr = (lane < DEG) ? adj[n * DEG + lane] : n;
        float x = g_sdst[h * N_NODES + n] + g_ssrc[h * N_NODES + nbr] + ba[h];
        sc = (x > 0.f) ? x : 0.2f * x;
    }

    float m = sc;
    #pragma unroll
    for (int off = 16; off > 0; off >>= 1)
        m = fmaxf(m, __shfl_xor_sync(0xFFFFFFFFu, m, off));

    float e = (lane < NBR) ? __expf(sc - m) : 0.f;
    float s = e;
    #pragma unroll
    for (int off = 16; off > 0; off >>= 1)
        s += __shfl_xor_sync(0xFFFFFFFFu, s, off);

    float alpha = e / s;

    float4 acc = make_float4(0.f, 0.f, 0.f, 0.f);
    #pragma unroll
    for (int d = 0; d < NBR; d++) {
        int nb = __shfl_sync(0xFFFFFFFFu, nbr, d);
        float al = __shfl_sync(0xFFFFFFFFu, alpha, d);
        uint2 pk = *(const uint2*)(g_hh + (size_t)nb * J_DIM + h * F_OUT + lane * 4);
        __half2 p0 = *(__half2*)&pk.x;
        __half2 p1 = *(__half2*)&pk.y;
        float2 f0 = __half22float2(p0);
        float2 f1 = __half22float2(p1);
        acc.x = fmaf(al, f0.x, acc.x);
        acc.y = fmaf(al, f0.y, acc.y);
        acc.z = fmaf(al, f1.x, acc.z);
        acc.w = fmaf(al, f1.y, acc.w);
    }
    *(float4*)(out + (size_t)n * J_DIM + h * F_OUT + lane * 4) = acc;
}

// ---------------------------------------------------------------------------
extern "C" void kernel_launch(void* const* d_in, const int* in_sizes, int n_in,
                              void* d_out, int out_size)
{
    const float* features = (const float*)d_in[0];   // [8192, 1024]
    const int*   adj      = (const int*)  d_in[1];   // [8192, 16]
    const float* W        = (const float*)d_in[2];   // [8, 1024, 128]
    const float* bW       = (const float*)d_in[3];   // [8, 128]
    const float* a        = (const float*)d_in[4];   // [8, 256]
    const float* ba       = (const float*)d_in[5];   // [8]
    float* out = (float*)d_out;                      // [8192, 1024]

    // 0) cast features / W to fp16 (W also transposed to K-major)
    castA<<<(N_NODES * F_IN) / (256 * 4), 256>>>(features);
    castW<<<dim3(F_OUT / 32, F_IN / 32, H_HEADS), dim3(32, 8)>>>(W);

    // 1) single-pass fp16 mma.sync projection GEMM (+ fused bias & score dots)
    const int dsmem = 68608;   // >= max(4*ARR_HF*2 = 40960, epilogue 67584)
    cudaFuncSetAttribute(gemm_tc, cudaFuncAttributeMaxDynamicSharedMemorySize, dsmem);
    gemm_tc<<<dim3(H_HEADS, N_NODES / 128), 256, dsmem>>>(bW, a);

    // 2) softmax + aggregate (fp16 gather)
    int warps = H_HEADS * N_NODES;
    attn_kernel<<<(warps * 32) / 256, 256>>>(adj, ba, out);
}